// round 8
// baseline (speedup 1.0000x reference)
#include <cuda_runtime.h>
#include <cstdint>

#define B_ 8
#define V_ 49
#define H_ 128
#define W_ 128
#define F_ 64

#define NROWS   (B_ * V_ * H_)            // 50176 output rows
#define GRID    (NROWS / 8)               // 6272 blocks, 8 rows (=8 h) per block
#define WAVE1   1184                      // 148 SMs x 8 resident blocks
#define LFI_BYTES ((size_t)NROWS * W_ * 4)        // 25,690,112
#define PF_BASE ((size_t)WAVE1 * 8 * W_ * 4)      // start of wave-2+ data
#define PF_CHUNK 17616                    // ceil((LFI_BYTES-PF_BASE)/WAVE1) to 16B
#define MSTRIDE 66                        // padded smem mask row (floats)

__device__ __forceinline__ void prefetch_l2(const void* p, uint32_t bytes) {
    asm volatile("cp.async.bulk.prefetch.L2.global [%0], %1;"
                 :: "l"(p), "r"(bytes) : "memory");
}

// Block = 8 consecutive rows = one (b,v) plane, h in [h0, h0+8). One warp/row.
__global__ void __launch_bounds__(256, 8)
depth_cue_kernel(const float4* __restrict__ lfi4,
                 const float* __restrict__ h_mask,
                 float2* __restrict__ out2) {
    __shared__ float m_s[8 * MSTRIDE];

    const int tid  = threadIdx.x;
    const int wid  = tid >> 5;
    const int lane = tid & 31;

    const int row0 = blockIdx.x << 3;
    const int b    = row0 / (V_ * H_);
    const int h0   = row0 & (H_ - 1);     // blocks are h-aligned (8 | 128)
    const int row  = row0 + wid;

    // 1) Own data load FIRST (longest latency; L2 hit for waves 2+)
    const float4 v4 = __ldcs(&lfi4[(size_t)row * 32 + lane]);

    // 2) Wave-ahead L2 warm: wave-1 blocks collectively prefetch ALL of
    //    waves 2..5's input (fire-and-forget, no SM-side load tracking).
    if (blockIdx.x < WAVE1 && tid == 0) {
        size_t beg = PF_BASE + (size_t)blockIdx.x * PF_CHUNK;
        size_t end = beg + PF_CHUNK;
        if (end > LFI_BYTES) end = LFI_BYTES;
        const char* base = (const char*)lfi4;
        for (size_t off = beg; off < end; off += 8192) {
            uint32_t sz = (uint32_t)((end - off) < 8192 ? (end - off) : 8192);
            prefetch_l2(base + off, sz);
        }
    }
    // Warm h_mask (256KB) for everyone: blocks 0..15 cover it in 16KB chunks.
    if (blockIdx.x < 16 && tid == 32) {
        prefetch_l2((const char*)h_mask + (size_t)blockIdx.x * 16384, 16384);
    }

    // 3) Mask gather for this block's 8 h-rows: m_s[h][f] = W * h_mask[b,f,h0+h].
    //    Lanes walk h-contiguously (8 consecutive h per f) -> 4 sectors/warp-instr.
    #pragma unroll
    for (int k = 0; k < 2; k++) {
        const int e  = tid + (k << 8);    // 0..511 over (f,h)
        const int f  = e >> 3;
        const int hh = e & 7;
        m_s[hh * MSTRIDE + f] =
            (float)W_ * __ldg(&h_mask[((b << 6) + f) * H_ + h0 + hh]);
    }

    // 4) Row-sum reduction (latency hidden by 64 resident warps/SM)
    float s = (v4.x + v4.y) + (v4.z + v4.w);
    #pragma unroll
    for (int o = 16; o > 0; o >>= 1)
        s += __shfl_xor_sync(0xffffffffu, s, o);

    // 5) Mask add + streaming store
    __syncthreads();
    const float2 m = *(const float2*)&m_s[wid * MSTRIDE + 2 * lane];
    __stcs(&out2[(size_t)row * 32 + lane], make_float2(s + m.x, s + m.y));
}

extern "C" void kernel_launch(void* const* d_in, const int* in_sizes, int n_in,
                              void* d_out, int out_size) {
    // Identify inputs by element count (robust to ordering):
    //   lfi    : B*V*H*W = 6,422,528
    //   f_maps : B*H*W*F = 8,388,608 (dead input — never touched)
    //   h_mask : B*F*H   = 65,536
    const float* lfi = nullptr;
    const float* h_mask = nullptr;
    for (int i = 0; i < n_in; i++) {
        if (in_sizes[i] == B_ * V_ * H_ * W_) lfi = (const float*)d_in[i];
        else if (in_sizes[i] == B_ * F_ * H_) h_mask = (const float*)d_in[i];
    }
    depth_cue_kernel<<<GRID, 256>>>((const float4*)lfi, h_mask, (float2*)d_out);
}

// round 9
// speedup vs baseline: 1.3934x; 1.3934x over previous
#include <cuda_runtime.h>
#include <cstdint>

#define B_ 8
#define V_ 49
#define H_ 128
#define W_ 128
#define F_ 64

#define LDG_ROWS 28        // v = 0..27  : 4 rows per warp via LDG.128
#define TMA_ROWS 21        // v = 28..48 : 3 rows per warp via cp.async.bulk -> smem
#define ROW_BYTES 512      // 128 floats
#define NTHREADS 224       // 7 warps

__device__ __forceinline__ uint32_t smem_u32(const void* p) {
    return (uint32_t)__cvta_generic_to_shared(p);
}
__device__ __forceinline__ void mbar_init(uint32_t bar, uint32_t cnt) {
    asm volatile("mbarrier.init.shared.b64 [%0], %1;" :: "r"(bar), "r"(cnt) : "memory");
}
__device__ __forceinline__ void mbar_expect_tx(uint32_t bar, uint32_t bytes) {
    asm volatile("mbarrier.arrive.expect_tx.shared.b64 _, [%0], %1;"
                 :: "r"(bar), "r"(bytes) : "memory");
}
__device__ __forceinline__ void mbar_wait(uint32_t bar, uint32_t parity) {
    asm volatile(
        "{\n\t.reg .pred P;\n\t"
        "WL_%=:\n\t"
        "mbarrier.try_wait.parity.acquire.cta.shared::cta.b64 P, [%0], %1, 0x989680;\n\t"
        "@P bra DONE_%=;\n\t"
        "bra WL_%=;\n\t"
        "DONE_%=:\n\t}"
        :: "r"(bar), "r"(parity) : "memory");
}
__device__ __forceinline__ void bulk_g2s(uint32_t dst, const void* src,
                                         uint32_t bytes, uint32_t bar) {
    asm volatile(
        "cp.async.bulk.shared::cluster.global.mbarrier::complete_tx::bytes "
        "[%0], [%1], %2, [%3];"
        :: "r"(dst), "l"(src), "r"(bytes), "r"(bar) : "memory");
}

// Block = one (b,h) pair (R4 geometry: minimal mask traffic, one wave of 1024
// blocks at 7 blocks/SM). Reads split across two independent HW paths:
//   v in [0,28): LDG.128, 4 rows/warp (the proven 2.78 TB/s leg)
//   v in [28,49): cp.async.bulk fired at t=0 into smem, consumed at the end
//                 (bulk-engine leg, latency hidden behind the whole LDG phase)
__global__ void __launch_bounds__(NTHREADS, 7)
depth_cue_kernel(const float* __restrict__ lfi,
                 const float* __restrict__ h_mask,
                 float2* __restrict__ out2) {
    __shared__ __align__(16) float buf[TMA_ROWS * W_];   // 10.5 KB
    __shared__ float m_s[F_];
    __shared__ __align__(8) unsigned long long bar[1];

    const int tid  = threadIdx.x;
    const int wid  = tid >> 5;
    const int lane = tid & 31;

    const int pair = blockIdx.x;          // b*128 + h
    const int b = pair >> 7;
    const int h = pair & (H_ - 1);

    // row v of this (b,h): lfi + ((b*49+v)*128 + h)*128 floats; v-stride = 16384 floats
    const float* row_base = lfi + ((size_t)(b * V_ * H_ + h)) * W_;

    const uint32_t baru = smem_u32(bar);
    if (tid == 0) {
        mbar_init(baru, 1);
        mbar_expect_tx(baru, TMA_ROWS * ROW_BYTES);
    }
    __syncthreads();   // expect_tx visible before any bulk copy fires

    // Fire the bulk leg: warp w's lane 0 copies smem rows t = 3w..3w+2 (v = 28+t)
    if (lane == 0) {
        const uint32_t dst0 = smem_u32(buf);
        #pragma unroll
        for (int k = 0; k < 3; k++) {
            const int t = wid * 3 + k;
            bulk_g2s(dst0 + (uint32_t)t * ROW_BYTES,
                     row_base + (size_t)(LDG_ROWS + t) * (H_ * W_),
                     ROW_BYTES, baru);
        }
    }

    // Scattered mask gather (once per block): m = W * h_mask[b,f,h]
    float mval = 0.0f;
    if (tid < F_) mval = (float)W_ * __ldg(&h_mask[((b << 6) + tid) * H_ + h]);

    // LDG leg: 4 front-batched coalesced rows per warp (v = 4w..4w+3)
    const float4* lfi4 = (const float4*)row_base;   // row v -> lfi4[v*4096 + lane]
    float s[4];
    #pragma unroll
    for (int r = 0; r < 4; r++) {
        const float4 x = lfi4[(size_t)(wid * 4 + r) * (H_ * W_ / 4) + lane];
        s[r] = (x.x + x.y) + (x.z + x.w);
    }
    if (tid < F_) m_s[tid] = mval;
    #pragma unroll
    for (int o = 16; o > 0; o >>= 1) {
        #pragma unroll
        for (int r = 0; r < 4; r++)
            s[r] += __shfl_xor_sync(0xffffffffu, s[r], o);
    }

    // Wait for bulk data + mask table
    mbar_wait(baru, 0);
    __syncthreads();

    const float2 m = ((const float2*)m_s)[lane];

    // Store LDG-leg rows
    #pragma unroll
    for (int r = 0; r < 4; r++) {
        const int v = wid * 4 + r;
        out2[((size_t)((b * V_ + v) * H_ + h)) * 32 + lane] =
            make_float2(s[r] + m.x, s[r] + m.y);
    }

    // Consume bulk-leg rows from smem: warp w handles t = 3w..3w+2 (v = 28+t)
    float q[3];
    #pragma unroll
    for (int k = 0; k < 3; k++) {
        const float4 y = ((const float4*)buf)[(wid * 3 + k) * 32 + lane];
        q[k] = (y.x + y.y) + (y.z + y.w);
    }
    #pragma unroll
    for (int o = 16; o > 0; o >>= 1) {
        #pragma unroll
        for (int k = 0; k < 3; k++)
            q[k] += __shfl_xor_sync(0xffffffffu, q[k], o);
    }
    #pragma unroll
    for (int k = 0; k < 3; k++) {
        const int v = LDG_ROWS + wid * 3 + k;
        out2[((size_t)((b * V_ + v) * H_ + h)) * 32 + lane] =
            make_float2(q[k] + m.x, q[k] + m.y);
    }
}

extern "C" void kernel_launch(void* const* d_in, const int* in_sizes, int n_in,
                              void* d_out, int out_size) {
    // Identify inputs by element count (robust to ordering):
    //   lfi    : B*V*H*W = 6,422,528
    //   f_maps : B*H*W*F = 8,388,608 (dead input — never touched)
    //   h_mask : B*F*H   = 65,536
    const float* lfi = nullptr;
    const float* h_mask = nullptr;
    for (int i = 0; i < n_in; i++) {
        if (in_sizes[i] == B_ * V_ * H_ * W_) lfi = (const float*)d_in[i];
        else if (in_sizes[i] == B_ * F_ * H_) h_mask = (const float*)d_in[i];
    }
    // 1024 blocks (one per (b,h)), 224 threads, one wave at 7 blocks/SM
    depth_cue_kernel<<<B_ * H_, NTHREADS>>>(lfi, h_mask, (float2*)d_out);
}